// round 16
// baseline (speedup 1.0000x reference)
#include <cuda_runtime.h>
#include <cstdint>
#include <cstddef>

#define T_  512
#define B_  32
#define D_  512
#define H_  1024
#define M_  (T_ * B_)      // 16384
#define BH_ (B_ * H_)      // 32768

#define KE0   3072         // layer0: 6 pairs x 512
#define NCH0  24
#define KE12  3072         // layers1,2: 3 planes x 1024
#define NCH12 24
#define MAXCH 24

// CTA tile 128(M) x 64(N), 128 threads, 2 CTAs/SM, 4-stage pipeline
#define NSTG 4
#define I8_STAGE 24576     // A 128x128B (16KB) + B 64x128B (8KB)
#define I8_BIAS_OFF (NSTG * I8_STAGE)          // 98304
#define I8_SMEM (I8_BIAS_OFF + 256 + 128)

// fused prep grid split (vec4: each block covers 1024 elements)
#define PREP_XBLKS  8192   // quant_x:  M_*D_ /1024
#define PREP_W0BLKS 512    // quant_w0: H_*D_ /1024
#define PREP_WBLKS  1024   // quant_w12: H_*H_ /1024 (x2 jobs)
#define PREP_TOTAL  (PREP_XBLKS + PREP_W0BLKS + 2 * PREP_WBLKS)   // 10752

// ---------------- scratch (static device globals) ----------------
__device__ __align__(256) char g_xq[3][M_ * D_];   // x planes s8 [T,B,D]
__device__ __align__(256) char g_spk[M_ * H_];     // spikes s8 [T,B,H]
__device__ float g_cur[M_ * H_];                   // currents fp32 [T,B,H]
__device__ __align__(256) char g_we0[H_ * KE0];    // layer0 extended weights
__device__ __align__(256) char g_we12[2][H_ * KE12];

// ---------------- PTX helpers ----------------
__device__ __forceinline__ uint32_t smem_u32(const void* p) {
    uint32_t a;
    asm("{ .reg .u64 t; cvta.to.shared.u64 t, %1; cvt.u32.u64 %0, t; }" : "=r"(a) : "l"(p));
    return a;
}
__device__ __forceinline__ void cp_async16(uint32_t saddr, const void* gaddr) {
    asm volatile("cp.async.cg.shared.global [%0], [%1], 16;" :: "r"(saddr), "l"(gaddr) : "memory");
}
__device__ __forceinline__ void cp_commit() {
    asm volatile("cp.async.commit_group;" ::: "memory");
}
__device__ __forceinline__ void cp_wait2() {
    asm volatile("cp.async.wait_group 2;" ::: "memory");
}
__device__ __forceinline__ void cp_wait1() {
    asm volatile("cp.async.wait_group 1;" ::: "memory");
}
__device__ __forceinline__ void cp_wait0() {
    asm volatile("cp.async.wait_group 0;" ::: "memory");
}
__device__ __forceinline__ void ldsm_x4(uint32_t* r, uint32_t addr) {
    asm volatile("ldmatrix.sync.aligned.m8n8.x4.shared.b16 {%0,%1,%2,%3}, [%4];"
                 : "=r"(r[0]), "=r"(r[1]), "=r"(r[2]), "=r"(r[3]) : "r"(addr));
}
__device__ __forceinline__ void imma16832(int* d, const uint32_t* a, uint32_t b0, uint32_t b1) {
    asm volatile(
        "mma.sync.aligned.m16n8k32.row.col.s32.s8.s8.s32 "
        "{%0,%1,%2,%3}, {%4,%5,%6,%7}, {%8,%9}, {%0,%1,%2,%3};"
        : "+r"(d[0]), "+r"(d[1]), "+r"(d[2]), "+r"(d[3])
        : "r"(a[0]), "r"(a[1]), "r"(a[2]), "r"(a[3]), "r"(b0), "r"(b1));
}

// ---------------- fused prep: all quantization jobs in ONE launch -------------
__device__ __forceinline__ void split3(float r, char* p) {
    #pragma unroll
    for (int g = 0; g < 3; g++) {
        float q = fminf(fmaxf(rintf(r), -127.0f), 127.0f);
        p[g] = (char)(int)q;
        r = (r - q) * 128.0f;
    }
}
__constant__ int c_wp0[6] = {0, 1, 0, 2, 1, 0};

__global__ void __launch_bounds__(256)
prep_all_kernel(const float* __restrict__ x,  const float* __restrict__ W0,
                const float* __restrict__ W1, const float* __restrict__ W2)
{
    const int bx  = blockIdx.x;
    const int tid = threadIdx.x;

    if (bx < PREP_XBLKS) {
        const int idx = ((bx * 256) + tid) * 4;
        const int d  = idx % D_;
        const int tb = idx / D_;
        const int b  = tb % B_;
        const int t  = tb / B_;
        float4 v = *(const float4*)(x + ((size_t)b * T_ + t) * D_ + d);
        char p0[3], p1[3], p2[3], p3[3];
        split3(v.x * 16.0f, p0); split3(v.y * 16.0f, p1);
        split3(v.z * 16.0f, p2); split3(v.w * 16.0f, p3);
        #pragma unroll
        for (int g = 0; g < 3; g++)
            *(char4*)&g_xq[g][idx] = make_char4(p0[g], p1[g], p2[g], p3[g]);
    } else if (bx < PREP_XBLKS + PREP_W0BLKS) {
        const int idx = ((bx - PREP_XBLKS) * 256 + tid) * 4;
        const int n = idx / D_, k = idx % D_;
        float4 v = *(const float4*)(W0 + idx);
        char p0[3], p1[3], p2[3], p3[3];
        split3(v.x * 2048.0f, p0); split3(v.y * 2048.0f, p1);
        split3(v.z * 2048.0f, p2); split3(v.w * 2048.0f, p3);
        #pragma unroll
        for (int pr = 0; pr < 6; pr++) {
            const int g = c_wp0[pr];
            *(char4*)&g_we0[(size_t)n * KE0 + pr * D_ + k] =
                make_char4(p0[g], p1[g], p2[g], p3[g]);
        }
    } else {
        const int rb  = bx - PREP_XBLKS - PREP_W0BLKS;
        const int job = rb / PREP_WBLKS;
        const float* W = job ? W2 : W1;
        char* dst = g_we12[job];
        const int idx = ((rb - job * PREP_WBLKS) * 256 + tid) * 4;
        const int n = idx / H_, k = idx % H_;
        float4 v = *(const float4*)(W + idx);
        char p0[3], p1[3], p2[3], p3[3];
        split3(v.x * 4096.0f, p0); split3(v.y * 4096.0f, p1);
        split3(v.z * 4096.0f, p2); split3(v.w * 4096.0f, p3);
        #pragma unroll
        for (int g = 0; g < 3; g++)
            *(char4*)&dst[(size_t)n * KE12 + (size_t)g * H_ + k] =
                make_char4(p0[g], p1[g], p2[g], p3[g]);
    }
}

// ---------------- int8 warp-IMMA GEMM: CTA 128x64, 128 threads, 2 CTAs/SM -----
// C = sum over scale-groups( fold_scale * exact_s32_partial ) + bias
// 4 warps (2m x 2n), warp tile 64x32, BK=128 int8, 4-stage cp.async,
// A-fragment double buffering across k32 steps (hides LDSM latency).
struct I8Args {
    const char* a_ptr[MAXCH];   // per-chunk A base (plane base + k offset)
    float       fold [MAXCH];   // 0 => no fold after this chunk
    const char* w;              // [H_, ke] extended weights
    const float* bias;
    float* c;
    int astride;                // A row stride (512 or 1024)
    int ke;                     // 3072
    int nchunk;                 // 24
};

__global__ void __launch_bounds__(128, 2)
gemm_i8(I8Args args)
{
    extern __shared__ char smem[];
    const uint32_t sb = smem_u32(smem);
    const int tid  = threadIdx.x;
    const int wid  = tid >> 5;
    const int lane = tid & 31;

    const int tile_n = blockIdx.x & 15;        // H/64 = 16
    const int tile_m = blockIdx.x >> 4;        // M/128 = 128
    const int m0 = tile_m * 128;
    const int n0 = tile_n * 64;

    float* bias_s = (float*)(smem + I8_BIAS_OFF);
    if (tid < 64) bias_s[tid] = args.bias[n0 + tid];

    const int lrow = tid >> 3;                 // 0..15
    const int lc   = tid & 7;                  // 0..7
    const int nch  = args.nchunk;

    auto load_stage = [&](int ch, int s) {
        const char* Ap = args.a_ptr[ch];
        const uint32_t sa = sb + s * I8_STAGE;
        const uint32_t sB = sa + 16384;
        #pragma unroll
        for (int p = 0; p < 8; p++) {          // A: 128 rows x 128B
            const int row = lrow + 16 * p;
            const uint32_t dst = sa + (uint32_t)(row * 128 + ((lc ^ (row & 7)) * 16));
            cp_async16(dst, Ap + (size_t)(m0 + row) * args.astride + lc * 16);
        }
        #pragma unroll
        for (int p = 0; p < 4; p++) {          // B: 64 rows x 128B
            const int row = lrow + 16 * p;
            const uint32_t dst = sB + (uint32_t)(row * 128 + ((lc ^ (row & 7)) * 16));
            cp_async16(dst, args.w + (size_t)(n0 + row) * args.ke + (size_t)ch * 128 + lc * 16);
        }
        cp_commit();
    };

    float facc[4][4][4];
    int   iacc[4][4][4];
    #pragma unroll
    for (int i = 0; i < 4; i++)
        #pragma unroll
        for (int j = 0; j < 4; j++)
            #pragma unroll
            for (int e = 0; e < 4; e++) { facc[i][j][e] = 0.0f; iacc[i][j][e] = 0; }

    const int wm = (wid & 1) * 64;             // 2 warps over M
    const int wn = (wid >> 1) * 32;            // 2 warps over N

    load_stage(0, 0);
    load_stage(1, 1);
    load_stage(2, 2);

    // A-fragment loader for one k32 step from stage base sa
    auto load_afrag = [&](uint32_t sa, int k32, uint32_t ar[4][4]) {
        #pragma unroll
        for (int mt = 0; mt < 4; mt++) {
            const int row = wm + mt * 16 + (lane & 15);
            const int c   = 2 * k32 + (lane >> 4);
            ldsm_x4(ar[mt], sa + (uint32_t)(row * 128 + ((c ^ (row & 7)) * 16)));
        }
    };

    #pragma unroll 1
    for (int ch = 0; ch < nch; ch++) {
        if (ch < nch - 2) cp_wait2();
        else if (ch == nch - 2) cp_wait1();
        else cp_wait0();
        __syncthreads();
        const int nc = ch + 3;
        if (nc < nch) load_stage(nc, nc % NSTG);

        const uint32_t sa = sb + (ch % NSTG) * I8_STAGE;
        const uint32_t sB = sa + 16384;

        uint32_t ar[2][4][4];
        load_afrag(sa, 0, ar[0]);              // prologue: k32=0 A frags

        #pragma unroll
        for (int k32 = 0; k32 < 4; k32++) {
            uint32_t br[2][4];
            #pragma unroll
            for (int nt = 0; nt < 2; nt++) {
                const int row = wn + nt * 16 + (lane & 7) + (lane >> 4) * 8;
                const int c   = 2 * k32 + ((lane >> 3) & 1);
                ldsm_x4(br[nt], sB + (uint32_t)(row * 128 + ((c ^ (row & 7)) * 16)));
            }
            if (k32 < 3) load_afrag(sa, k32 + 1, ar[(k32 + 1) & 1]);
            const uint32_t (*ac)[4] = ar[k32 & 1];
            #pragma unroll
            for (int mt = 0; mt < 4; mt++)
                #pragma unroll
                for (int nt = 0; nt < 2; nt++) {
                    imma16832(iacc[mt][2 * nt],     ac[mt], br[nt][0], br[nt][1]);
                    imma16832(iacc[mt][2 * nt + 1], ac[mt], br[nt][2], br[nt][3]);
                }
        }

        const float fs = args.fold[ch];
        if (fs != 0.0f) {                      // exact power-of-2 scale fold
            #pragma unroll
            for (int mt = 0; mt < 4; mt++)
                #pragma unroll
                for (int j = 0; j < 4; j++)
                    #pragma unroll
                    for (int e = 0; e < 4; e++) {
                        facc[mt][j][e] += (float)iacc[mt][j][e] * fs;
                        iacc[mt][j][e] = 0;
                    }
        }
    }
    __syncthreads();

    // epilogue: facc -> smem -> coalesced stores (+bias)
    float* stg = (float*)smem;                 // 128 x 68 floats (34.8 KB)
    #pragma unroll
    for (int mt = 0; mt < 4; mt++) {
        #pragma unroll
        for (int j = 0; j < 4; j++) {
            const int r0 = wm + mt * 16 + lane / 4;
            const int cc = wn + j * 8 + 2 * (lane % 4);
            stg[r0 * 68 + cc]           = facc[mt][j][0];
            stg[r0 * 68 + cc + 1]       = facc[mt][j][1];
            stg[(r0 + 8) * 68 + cc]     = facc[mt][j][2];
            stg[(r0 + 8) * 68 + cc + 1] = facc[mt][j][3];
        }
    }
    __syncthreads();
    #pragma unroll 4
    for (int it = 0; it < 16; it++) {
        const int idx = it * 512 + tid * 4;
        const int row = idx >> 6, col = idx & 63;
        float4 v = *(const float4*)&stg[row * 68 + col];
        v.x += bias_s[col];
        v.y += bias_s[col + 1];
        v.z += bias_s[col + 2];
        v.w += bias_s[col + 3];
        *(float4*)&args.c[(size_t)(m0 + row) * H_ + n0 + col] = v;
    }
}

// ---------------- serial LIF scan (scalar; 32768 threads for latency cover) ----
template<bool FINAL_OUT>
__global__ void scan_kernel(const float* __restrict__ I,
                            char* __restrict__ Sb,
                            float* __restrict__ Of)
{
    int idx = blockIdx.x * blockDim.x + threadIdx.x;   // 0..BH_-1
    if (idx >= BH_) return;
    const int b = idx / H_;
    const int h = idx % H_;
    float u = 0.0f;
    #pragma unroll 16
    for (int t = 0; t < T_; t++) {
        float cur = I[(size_t)t * BH_ + idx];
        u = 0.5f * u + cur;
        float v = u - 0.5f;
        bool fire = (v >= 0.0f);
        if (FINAL_OUT) Of[((size_t)b * T_ + t) * H_ + h] = fire ? 1.0f : 0.0f;
        else           Sb[(size_t)t * BH_ + idx] = fire ? 1 : 0;
        u = fire ? 0.0f : u;
    }
}

// ---------------- launch ----------------
extern "C" void kernel_launch(void* const* d_in, const int* in_sizes, int n_in,
                              void* d_out, int out_size)
{
    const float* x  = (const float*)d_in[0];
    const float* W0 = (const float*)d_in[1];
    const float* b0 = (const float*)d_in[2];
    const float* W1 = (const float*)d_in[3];
    const float* b1 = (const float*)d_in[4];
    const float* W2 = (const float*)d_in[5];
    const float* b2 = (const float*)d_in[6];
    float* out = (float*)d_out;

    char *xq, *spk, *we0, *we12;
    float* cur;
    cudaGetSymbolAddress((void**)&xq,   g_xq);
    cudaGetSymbolAddress((void**)&spk,  g_spk);
    cudaGetSymbolAddress((void**)&cur,  g_cur);
    cudaGetSymbolAddress((void**)&we0,  g_we0);
    cudaGetSymbolAddress((void**)&we12, g_we12);
    char* we1 = we12;
    char* we2 = we12 + (size_t)H_ * KE12;

    cudaFuncSetAttribute(gemm_i8, cudaFuncAttributeMaxDynamicSharedMemorySize, I8_SMEM);

    // fused prep: quant_x + quant_w0 + quant_w1 + quant_w2 in one launch
    prep_all_kernel<<<PREP_TOTAL, 256>>>(x, W0, W1, W2);

    const int GRID = (M_ / 128) * (H_ / 64);   // 2048 CTAs

    // Layer 0: pairs (x_i, w_j), s=i+j<=2: p -> x {0, 0,1, 0,1,2}, w {0, 1,0, 2,1,0}
    // scale groups by s: chunks [0..3]=s0, [4..11]=s1, [12..23]=s2; Sx*Sw = 2^15.
    {
        I8Args a = {};
        const int xp[6] = {0, 0, 1, 0, 1, 2};
        for (int ch = 0; ch < NCH0; ch++) {
            int p = ch >> 2;
            a.a_ptr[ch] = xq + (size_t)xp[p] * (M_ * D_) + (ch & 3) * 128;
            a.fold[ch] = 0.0f;
        }
        a.fold[3]  = 3.0517578125e-05f;        // 2^-15
        a.fold[11] = 2.384185791015625e-07f;   // 2^-22
        a.fold[23] = 1.862645149230957e-09f;   // 2^-29
        a.w = we0; a.bias = b0; a.c = cur;
        a.astride = D_; a.ke = KE0; a.nchunk = NCH0;
        gemm_i8<<<GRID, 128, I8_SMEM>>>(a);
    }
    scan_kernel<false><<<BH_ / 256, 256>>>(cur, spk, nullptr);

    // Layers 1 & 2: 3 weight planes, Sw = 2^12.
    for (int layer = 1; layer <= 2; layer++) {
        I8Args a = {};
        for (int ch = 0; ch < NCH12; ch++) {
            a.a_ptr[ch] = spk + (ch & 7) * 128;
            a.fold[ch] = 0.0f;
        }
        a.fold[7]  = 2.44140625e-04f;          // 2^-12
        a.fold[15] = 1.9073486328125e-06f;     // 2^-19
        a.fold[23] = 1.4901161193847656e-08f;  // 2^-26
        a.w = (layer == 1) ? we1 : we2;
        a.bias = (layer == 1) ? b1 : b2;
        a.c = cur;
        a.astride = H_; a.ke = KE12; a.nchunk = NCH12;
        gemm_i8<<<GRID, 128, I8_SMEM>>>(a);
        if (layer == 1) scan_kernel<false><<<BH_ / 256, 256>>>(cur, spk, nullptr);
        else            scan_kernel<true> <<<BH_ / 256, 256>>>(cur, nullptr, out);
    }
}

// round 17
// speedup vs baseline: 1.0076x; 1.0076x over previous
#include <cuda_runtime.h>
#include <cstdint>
#include <cstddef>

#define T_  512
#define B_  32
#define D_  512
#define H_  1024
#define M_  (T_ * B_)      // 16384
#define BH_ (B_ * H_)      // 32768

#define KE0   3072         // layer0: 6 pairs x 512
#define NCH0  24
#define KE12  3072         // layers1,2: 3 planes x 1024
#define NCH12 24
#define MAXCH 24

// CTA tile 128(M) x 64(N), 128 threads, 2 CTAs/SM, 4 stages = 2 double-buffers
#define NSTG 4
#define I8_STAGE 24576     // A 128x128B (16KB) + B 64x128B (8KB)
#define I8_BIAS_OFF (NSTG * I8_STAGE)          // 98304
#define I8_SMEM (I8_BIAS_OFF + 256 + 128)

// fused prep grid split (vec4: each block covers 1024 elements)
#define PREP_XBLKS  8192   // quant_x:  M_*D_ /1024
#define PREP_W0BLKS 512    // quant_w0: H_*D_ /1024
#define PREP_WBLKS  1024   // quant_w12: H_*H_ /1024 (x2 jobs)
#define PREP_TOTAL  (PREP_XBLKS + PREP_W0BLKS + 2 * PREP_WBLKS)   // 10752

// ---------------- scratch (static device globals) ----------------
__device__ __align__(256) char g_xq[3][M_ * D_];   // x planes s8 [T,B,D]
__device__ __align__(256) char g_spk[M_ * H_];     // spikes s8 [T,B,H]
__device__ float g_cur[M_ * H_];                   // currents fp32 [T,B,H]
__device__ __align__(256) char g_we0[H_ * KE0];    // layer0 extended weights
__device__ __align__(256) char g_we12[2][H_ * KE12];

// ---------------- PTX helpers ----------------
__device__ __forceinline__ uint32_t smem_u32(const void* p) {
    uint32_t a;
    asm("{ .reg .u64 t; cvta.to.shared.u64 t, %1; cvt.u32.u64 %0, t; }" : "=r"(a) : "l"(p));
    return a;
}
__device__ __forceinline__ void cp_async16(uint32_t saddr, const void* gaddr) {
    asm volatile("cp.async.cg.shared.global [%0], [%1], 16;" :: "r"(saddr), "l"(gaddr) : "memory");
}
__device__ __forceinline__ void cp_commit() {
    asm volatile("cp.async.commit_group;" ::: "memory");
}
__device__ __forceinline__ void cp_wait0() {
    asm volatile("cp.async.wait_group 0;" ::: "memory");
}
__device__ __forceinline__ void ldsm_x4(uint32_t* r, uint32_t addr) {
    asm volatile("ldmatrix.sync.aligned.m8n8.x4.shared.b16 {%0,%1,%2,%3}, [%4];"
                 : "=r"(r[0]), "=r"(r[1]), "=r"(r[2]), "=r"(r[3]) : "r"(addr));
}
__device__ __forceinline__ void imma16832(int* d, const uint32_t* a, uint32_t b0, uint32_t b1) {
    asm volatile(
        "mma.sync.aligned.m16n8k32.row.col.s32.s8.s8.s32 "
        "{%0,%1,%2,%3}, {%4,%5,%6,%7}, {%8,%9}, {%0,%1,%2,%3};"
        : "+r"(d[0]), "+r"(d[1]), "+r"(d[2]), "+r"(d[3])
        : "r"(a[0]), "r"(a[1]), "r"(a[2]), "r"(a[3]), "r"(b0), "r"(b1));
}

// ---------------- fused prep: all quantization jobs in ONE launch -------------
__device__ __forceinline__ void split3(float r, char* p) {
    #pragma unroll
    for (int g = 0; g < 3; g++) {
        float q = fminf(fmaxf(rintf(r), -127.0f), 127.0f);
        p[g] = (char)(int)q;
        r = (r - q) * 128.0f;
    }
}
__constant__ int c_wp0[6] = {0, 1, 0, 2, 1, 0};

__global__ void __launch_bounds__(256)
prep_all_kernel(const float* __restrict__ x,  const float* __restrict__ W0,
                const float* __restrict__ W1, const float* __restrict__ W2)
{
    const int bx  = blockIdx.x;
    const int tid = threadIdx.x;

    if (bx < PREP_XBLKS) {
        const int idx = ((bx * 256) + tid) * 4;
        const int d  = idx % D_;
        const int tb = idx / D_;
        const int b  = tb % B_;
        const int t  = tb / B_;
        float4 v = *(const float4*)(x + ((size_t)b * T_ + t) * D_ + d);
        char p0[3], p1[3], p2[3], p3[3];
        split3(v.x * 16.0f, p0); split3(v.y * 16.0f, p1);
        split3(v.z * 16.0f, p2); split3(v.w * 16.0f, p3);
        #pragma unroll
        for (int g = 0; g < 3; g++)
            *(char4*)&g_xq[g][idx] = make_char4(p0[g], p1[g], p2[g], p3[g]);
    } else if (bx < PREP_XBLKS + PREP_W0BLKS) {
        const int idx = ((bx - PREP_XBLKS) * 256 + tid) * 4;
        const int n = idx / D_, k = idx % D_;
        float4 v = *(const float4*)(W0 + idx);
        char p0[3], p1[3], p2[3], p3[3];
        split3(v.x * 2048.0f, p0); split3(v.y * 2048.0f, p1);
        split3(v.z * 2048.0f, p2); split3(v.w * 2048.0f, p3);
        #pragma unroll
        for (int pr = 0; pr < 6; pr++) {
            const int g = c_wp0[pr];
            *(char4*)&g_we0[(size_t)n * KE0 + pr * D_ + k] =
                make_char4(p0[g], p1[g], p2[g], p3[g]);
        }
    } else {
        const int rb  = bx - PREP_XBLKS - PREP_W0BLKS;
        const int job = rb / PREP_WBLKS;
        const float* W = job ? W2 : W1;
        char* dst = g_we12[job];
        const int idx = ((rb - job * PREP_WBLKS) * 256 + tid) * 4;
        const int n = idx / H_, k = idx % H_;
        float4 v = *(const float4*)(W + idx);
        char p0[3], p1[3], p2[3], p3[3];
        split3(v.x * 4096.0f, p0); split3(v.y * 4096.0f, p1);
        split3(v.z * 4096.0f, p2); split3(v.w * 4096.0f, p3);
        #pragma unroll
        for (int g = 0; g < 3; g++)
            *(char4*)&dst[(size_t)n * KE12 + (size_t)g * H_ + k] =
                make_char4(p0[g], p1[g], p2[g], p3[g]);
    }
}

// ---------------- int8 warp-IMMA GEMM: CTA 128x64, 128 threads, 2 CTAs/SM -----
// C = sum over scale-groups( fold_scale * exact_s32_partial ) + bias
// 4 warps (2m x 2n), warp tile 64x32, 2-chunk epochs over 2 double-buffers:
// per epoch ONE wait0 + ONE barrier, one 24-op cp.async burst, 2 chunks of IMMA.
struct I8Args {
    const char* a_ptr[MAXCH];   // per-chunk A base (plane base + k offset)
    float       fold [MAXCH];   // 0 => no fold after this chunk
    const char* w;              // [H_, ke] extended weights
    const float* bias;
    float* c;
    int astride;                // A row stride (512 or 1024)
    int ke;                     // 3072
    int nchunk;                 // 24 (even)
};

__global__ void __launch_bounds__(128, 2)
gemm_i8(I8Args args)
{
    extern __shared__ char smem[];
    const uint32_t sb = smem_u32(smem);
    const int tid  = threadIdx.x;
    const int wid  = tid >> 5;
    const int lane = tid & 31;

    const int tile_n = blockIdx.x & 15;        // H/64 = 16
    const int tile_m = blockIdx.x >> 4;        // M/128 = 128
    const int m0 = tile_m * 128;
    const int n0 = tile_n * 64;

    float* bias_s = (float*)(smem + I8_BIAS_OFF);
    if (tid < 64) bias_s[tid] = args.bias[n0 + tid];

    const int lrow = tid >> 3;                 // 0..15
    const int lc   = tid & 7;                  // 0..7
    const int neps = args.nchunk >> 1;         // 12 epochs

    // load one chunk into physical stage s (no commit)
    auto load_chunk = [&](int ch, int s) {
        const char* Ap = args.a_ptr[ch];
        const uint32_t sa = sb + s * I8_STAGE;
        const uint32_t sB = sa + 16384;
        #pragma unroll
        for (int p = 0; p < 8; p++) {          // A: 128 rows x 128B
            const int row = lrow + 16 * p;
            const uint32_t dst = sa + (uint32_t)(row * 128 + ((lc ^ (row & 7)) * 16));
            cp_async16(dst, Ap + (size_t)(m0 + row) * args.astride + lc * 16);
        }
        #pragma unroll
        for (int p = 0; p < 4; p++) {          // B: 64 rows x 128B
            const int row = lrow + 16 * p;
            const uint32_t dst = sB + (uint32_t)(row * 128 + ((lc ^ (row & 7)) * 16));
            cp_async16(dst, args.w + (size_t)(n0 + row) * args.ke + (size_t)ch * 128 + lc * 16);
        }
    };
    // load both chunks of epoch e into its double-buffer, single commit
    auto load_epoch = [&](int e) {
        const int s0 = (e & 1) * 2;
        load_chunk(2 * e,     s0);
        load_chunk(2 * e + 1, s0 + 1);
        cp_commit();
    };

    float facc[4][4][4];
    int   iacc[4][4][4];
    #pragma unroll
    for (int i = 0; i < 4; i++)
        #pragma unroll
        for (int j = 0; j < 4; j++)
            #pragma unroll
            for (int e = 0; e < 4; e++) { facc[i][j][e] = 0.0f; iacc[i][j][e] = 0; }

    const int wm = (wid & 1) * 64;             // 2 warps over M
    const int wn = (wid >> 1) * 32;            // 2 warps over N

    // A-fragment loader for one k32 step from stage base sa
    auto load_afrag = [&](uint32_t sa, int k32, uint32_t ar[4][4]) {
        #pragma unroll
        for (int mt = 0; mt < 4; mt++) {
            const int row = wm + mt * 16 + (lane & 15);
            const int c   = 2 * k32 + (lane >> 4);
            ldsm_x4(ar[mt], sa + (uint32_t)(row * 128 + ((c ^ (row & 7)) * 16)));
        }
    };

    load_epoch(0);

    #pragma unroll 1
    for (int e = 0; e < neps; e++) {
        cp_wait0();                            // epoch e resident
        __syncthreads();                       // publish to all warps; prior buffer free
        if (e + 1 < neps) load_epoch(e + 1);   // prefetch next epoch (other buffer)

        #pragma unroll
        for (int half = 0; half < 2; half++) {
            const int ch = 2 * e + half;
            const uint32_t sa = sb + ((e & 1) * 2 + half) * I8_STAGE;
            const uint32_t sB = sa + 16384;

            uint32_t ar[2][4][4];
            load_afrag(sa, 0, ar[0]);

            #pragma unroll
            for (int k32 = 0; k32 < 4; k32++) {
                uint32_t br[2][4];
                #pragma unroll
                for (int nt = 0; nt < 2; nt++) {
                    const int row = wn + nt * 16 + (lane & 7) + (lane >> 4) * 8;
                    const int c   = 2 * k32 + ((lane >> 3) & 1);
                    ldsm_x4(br[nt], sB + (uint32_t)(row * 128 + ((c ^ (row & 7)) * 16)));
                }
                if (k32 < 3) load_afrag(sa, k32 + 1, ar[(k32 + 1) & 1]);
                const uint32_t (*ac)[4] = ar[k32 & 1];
                #pragma unroll
                for (int mt = 0; mt < 4; mt++)
                    #pragma unroll
                    for (int nt = 0; nt < 2; nt++) {
                        imma16832(iacc[mt][2 * nt],     ac[mt], br[nt][0], br[nt][1]);
                        imma16832(iacc[mt][2 * nt + 1], ac[mt], br[nt][2], br[nt][3]);
                    }
            }

            const float fs = args.fold[ch];
            if (fs != 0.0f) {                  // exact power-of-2 scale fold
                #pragma unroll
                for (int mt = 0; mt < 4; mt++)
                    #pragma unroll
                    for (int j = 0; j < 4; j++)
                        #pragma unroll
                        for (int ee = 0; ee < 4; ee++) {
                            facc[mt][j][ee] += (float)iacc[mt][j][ee] * fs;
                            iacc[mt][j][ee] = 0;
                        }
            }
        }
    }
    __syncthreads();

    // epilogue: facc -> smem -> coalesced stores (+bias)
    float* stg = (float*)smem;                 // 128 x 68 floats (34.8 KB)
    #pragma unroll
    for (int mt = 0; mt < 4; mt++) {
        #pragma unroll
        for (int j = 0; j < 4; j++) {
            const int r0 = wm + mt * 16 + lane / 4;
            const int cc = wn + j * 8 + 2 * (lane % 4);
            stg[r0 * 68 + cc]           = facc[mt][j][0];
            stg[r0 * 68 + cc + 1]       = facc[mt][j][1];
            stg[(r0 + 8) * 68 + cc]     = facc[mt][j][2];
            stg[(r0 + 8) * 68 + cc + 1] = facc[mt][j][3];
        }
    }
    __syncthreads();
    #pragma unroll 4
    for (int it = 0; it < 16; it++) {
        const int idx = it * 512 + tid * 4;
        const int row = idx >> 6, col = idx & 63;
        float4 v = *(const float4*)&stg[row * 68 + col];
        v.x += bias_s[col];
        v.y += bias_s[col + 1];
        v.z += bias_s[col + 2];
        v.w += bias_s[col + 3];
        *(float4*)&args.c[(size_t)(m0 + row) * H_ + n0 + col] = v;
    }
}

// ---------------- serial LIF scan (scalar; 32768 threads for latency cover) ----
template<bool FINAL_OUT>
__global__ void scan_kernel(const float* __restrict__ I,
                            char* __restrict__ Sb,
                            float* __restrict__ Of)
{
    int idx = blockIdx.x * blockDim.x + threadIdx.x;   // 0..BH_-1
    if (idx >= BH_) return;
    const int b = idx / H_;
    const int h = idx % H_;
    float u = 0.0f;
    #pragma unroll 16
    for (int t = 0; t < T_; t++) {
        float cur = I[(size_t)t * BH_ + idx];
        u = 0.5f * u + cur;
        float v = u - 0.5f;
        bool fire = (v >= 0.0f);
        if (FINAL_OUT) Of[((size_t)b * T_ + t) * H_ + h] = fire ? 1.0f : 0.0f;
        else           Sb[(size_t)t * BH_ + idx] = fire ? 1 : 0;
        u = fire ? 0.0f : u;
    }
}

// ---------------- launch ----------------
extern "C" void kernel_launch(void* const* d_in, const int* in_sizes, int n_in,
                              void* d_out, int out_size)
{
    const float* x  = (const float*)d_in[0];
    const float* W0 = (const float*)d_in[1];
    const float* b0 = (const float*)d_in[2];
    const float* W1 = (const float*)d_in[3];
    const float* b1 = (const float*)d_in[4];
    const float* W2 = (const float*)d_in[5];
    const float* b2 = (const float*)d_in[6];
    float* out = (float*)d_out;

    char *xq, *spk, *we0, *we12;
    float* cur;
    cudaGetSymbolAddress((void**)&xq,   g_xq);
    cudaGetSymbolAddress((void**)&spk,  g_spk);
    cudaGetSymbolAddress((void**)&cur,  g_cur);
    cudaGetSymbolAddress((void**)&we0,  g_we0);
    cudaGetSymbolAddress((void**)&we12, g_we12);
    char* we1 = we12;
    char* we2 = we12 + (size_t)H_ * KE12;

    cudaFuncSetAttribute(gemm_i8, cudaFuncAttributeMaxDynamicSharedMemorySize, I8_SMEM);

    // fused prep: quant_x + quant_w0 + quant_w1 + quant_w2 in one launch
    prep_all_kernel<<<PREP_TOTAL, 256>>>(x, W0, W1, W2);

    const int GRID = (M_ / 128) * (H_ / 64);   // 2048 CTAs

    // Layer 0: pairs (x_i, w_j), s=i+j<=2: p -> x {0, 0,1, 0,1,2}, w {0, 1,0, 2,1,0}
    // scale groups by s: chunks [0..3]=s0, [4..11]=s1, [12..23]=s2; Sx*Sw = 2^15.
    {
        I8Args a = {};
        const int xp[6] = {0, 0, 1, 0, 1, 2};
        for (int ch = 0; ch < NCH0; ch++) {
            int p = ch >> 2;
            a.a_ptr[ch] = xq + (size_t)xp[p] * (M_ * D_) + (ch & 3) * 128;
            a.fold[ch] = 0.0f;
        }
        a.fold[3]  = 3.0517578125e-05f;        // 2^-15
        a.fold[11] = 2.384185791015625e-07f;   // 2^-22
        a.fold[23] = 1.862645149230957e-09f;   // 2^-29
        a.w = we0; a.bias = b0; a.c = cur;
        a.astride = D_; a.ke = KE0; a.nchunk = NCH0;
        gemm_i8<<<GRID, 128, I8_SMEM>>>(a);
    }
    scan_kernel<false><<<BH_ / 256, 256>>>(cur, spk, nullptr);

    // Layers 1 & 2: 3 weight planes, Sw = 2^12.
    for (int layer = 1; layer <= 2; layer++) {
        I8Args a = {};
        for (int ch = 0; ch < NCH12; ch++) {
            a.a_ptr[ch] = spk + (ch & 7) * 128;
            a.fold[ch] = 0.0f;
        }
        a.fold[7]  = 2.44140625e-04f;          // 2^-12
        a.fold[15] = 1.9073486328125e-06f;     // 2^-19
        a.fold[23] = 1.4901161193847656e-08f;  // 2^-26
        a.w = (layer == 1) ? we1 : we2;
        a.bias = (layer == 1) ? b1 : b2;
        a.c = cur;
        a.astride = H_; a.ke = KE12; a.nchunk = NCH12;
        gemm_i8<<<GRID, 128, I8_SMEM>>>(a);
        if (layer == 1) scan_kernel<false><<<BH_ / 256, 256>>>(cur, spk, nullptr);
        else            scan_kernel<true> <<<BH_ / 256, 256>>>(cur, nullptr, out);
    }
}